// round 5
// baseline (speedup 1.0000x reference)
#include <cuda_runtime.h>
#include <math.h>

#define B_    4
#define S_    8192
#define H_    16
#define D_    128
#define NB_   64
#define BS_   128
#define HID_  32
#define HID2_ 16
#define KPAIRS_ 1024

// scratch (no cudaMalloc allowed)
__device__ float g_qimp [B_*NB_*H_];
__device__ float g_kimp [B_*NB_*H_];
__device__ float g_qpart[B_*NB_*H_*HID_];
__device__ float g_kpart[B_*NB_*H_*HID_];
__device__ float g_comb [B_*NB_*NB_*H_];

// ---------------------------------------------------------------------------
// K1: block-mean pooling + importance MLP + interaction first-linear split.
// grid = B*NB*H = 4096 blocks, 128 threads (one thread per D element).
// ---------------------------------------------------------------------------
__global__ void pool_mlp_kernel(
    const float* __restrict__ q,  const float* __restrict__ k,
    const float* __restrict__ w1, const float* __restrict__ b1,
    const float* __restrict__ w2, const float* __restrict__ b2,
    const float* __restrict__ w3, const float* __restrict__ b3,
    const float* __restrict__ wi1)
{
    const int idx = blockIdx.x;
    const int b   = idx >> 10;          // / (NB*H)
    const int r   = idx & 1023;
    const int blk = r >> 4;
    const int h   = r & 15;
    const int tid = threadIdx.x;        // 0..127 == d

    __shared__ float avg[2][D_];
    __shared__ float h1s[2][HID_];
    __shared__ float h2s[2][HID2_];

    // mean over the 128 rows of this block; stride between rows = H*D floats
    const size_t base = ((((size_t)b*S_) + (size_t)blk*BS_)*H_ + h)*D_ + tid;
    float sq = 0.f, sk = 0.f;
    #pragma unroll 8
    for (int s = 0; s < BS_; s++) {
        sq += q[base + (size_t)s*(H_*D_)];
        sk += k[base + (size_t)s*(H_*D_)];
    }
    avg[0][tid] = sq * (1.0f/128.0f);
    avg[1][tid] = sk * (1.0f/128.0f);
    __syncthreads();

    if (tid < 64) {
        // importance layer 1: 2 tensors x 32 hidden
        const int t = (tid >= 32);
        const int j = tid & 31;
        const float* av = avg[t];
        float acc = b1[j];
        #pragma unroll 8
        for (int d = 0; d < D_; d++) acc = fmaf(av[d], w1[d*HID_ + j], acc);
        h1s[t][j] = fmaxf(acc, 0.f);
    } else {
        // interaction first linear (split, no bias here): 2 tensors x 32
        const int t2 = tid - 64;
        const int t  = (t2 >= 32);
        const int j  = t2 & 31;
        const float* av = avg[t];
        float acc = 0.f;
        #pragma unroll 8
        for (int d = 0; d < D_; d++)
            acc = fmaf(av[d], wi1[(t*D_ + d)*HID_ + j], acc);
        float* gp = t ? g_kpart : g_qpart;
        gp[(((size_t)b*NB_ + blk)*H_ + h)*HID_ + j] = acc;
    }
    __syncthreads();

    if (tid < 32) {
        const int t = (tid >= 16);
        const int j = tid & 15;
        float acc = b2[j];
        #pragma unroll
        for (int m = 0; m < HID_; m++) acc = fmaf(h1s[t][m], w2[m*HID2_ + j], acc);
        h2s[t][j] = fmaxf(acc, 0.f);
    }
    __syncthreads();

    if (tid < 2) {
        float acc = b3[0];
        #pragma unroll
        for (int m = 0; m < HID2_; m++) acc = fmaf(h2s[tid][m], w3[m], acc);
        const float imp = 1.f / (1.f + expf(-acc));
        float* gi = tid ? g_kimp : g_qimp;
        gi[((size_t)b*NB_ + blk)*H_ + h] = imp;
    }
}

// ---------------------------------------------------------------------------
// K2: interaction MLP + combined score.
// grid = B*NB (one block per (b, i)), 256 threads.
// ---------------------------------------------------------------------------
__global__ void interact_kernel(
    const float* __restrict__ bi1,
    const float* __restrict__ wi2,
    const float* __restrict__ bi2)
{
    const int b   = blockIdx.x >> 6;
    const int i   = blockIdx.x & 63;
    const int tid = threadIdx.x;

    __shared__ float qp[H_*HID_];
    __shared__ float qi[H_];
    __shared__ float bw[HID_];
    __shared__ float wv[HID_];

    for (int t = tid; t < H_*HID_; t += 256)
        qp[t] = g_qpart[((size_t)(b*NB_ + i)*H_)*HID_ + t];
    if (tid < H_)   qi[tid] = g_qimp[(b*NB_ + i)*H_ + tid];
    if (tid < HID_) { bw[tid] = bi1[tid]; wv[tid] = wi2[tid]; }
    __syncthreads();

    const float b2v = bi2[0];
    for (int t = tid; t < NB_*H_; t += 256) {
        const int j = t >> 4;
        const int h = t & 15;
        const float* kp  = &g_kpart[((size_t)(b*NB_ + j)*H_ + h)*HID_];
        const float* qph = &qp[h*HID_];
        float acc = b2v;
        #pragma unroll
        for (int m = 0; m < HID_; m++) {
            const float v = qph[m] + kp[m] + bw[m];
            acc = fmaf(fmaxf(v, 0.f), wv[m], acc);
        }
        const float inter = 1.f / (1.f + expf(-acc));
        const float c = qi[h] * g_kimp[(b*NB_ + j)*H_ + h] * inter;
        g_comb[(((size_t)b*NB_ + i)*NB_ + j)*H_ + h] = c;
    }
}

// ---------------------------------------------------------------------------
// K3: exact top-1024-of-4096 per flat row (b, fh). The reference's raw
// reshape means row (b,fh) = 4096 CONTIGUOUS elements of g_comb, and the
// output mask lands at the SAME contiguous offsets of out.
// Output dtype is float32 (bool promoted by the harness): write 1.0f/0.0f.
// grid = B*H = 64 blocks, 256 threads.
// ---------------------------------------------------------------------------
__global__ void topk_kernel(float* __restrict__ out)
{
    const int row = blockIdx.x;     // b*16 + fh
    const int tid = threadIdx.x;

    __shared__ unsigned int keys[4096];
    __shared__ int red[256];
    __shared__ int wred[8];
    __shared__ int bcast;

    const float* src = g_comb + (size_t)row * 4096;
    for (int t = tid; t < 4096; t += 256)
        keys[t] = __float_as_uint(src[t]);   // all values > 0 -> monotone bits
    __syncthreads();

    const int lane = tid & 31;
    const int warp = tid >> 5;

    // binary search for T = 1024th largest key (max u with count(>=u) >= 1024)
    unsigned int lo = 0u, hi = 0xFFFFFFFFu;
    while (lo < hi) {
        const unsigned int mid = lo + ((hi - lo) >> 1) + 1u;
        int cnt = 0;
        #pragma unroll
        for (int u = 0; u < 16; u++) cnt += (keys[tid*16 + u] >= mid);
        #pragma unroll
        for (int o = 16; o > 0; o >>= 1) cnt += __shfl_down_sync(0xFFFFFFFFu, cnt, o);
        if (lane == 0) wred[warp] = cnt;
        __syncthreads();
        if (tid == 0) {
            int tot = 0;
            #pragma unroll
            for (int w = 0; w < 8; w++) tot += wred[w];
            bcast = tot;
        }
        __syncthreads();
        const int total = bcast;
        __syncthreads();
        if (total >= KPAIRS_) lo = mid; else hi = mid - 1u;
    }
    const unsigned int T = lo;

    // count strictly greater than T
    {
        int cnt = 0;
        #pragma unroll
        for (int u = 0; u < 16; u++) cnt += (keys[tid*16 + u] > T);
        #pragma unroll
        for (int o = 16; o > 0; o >>= 1) cnt += __shfl_down_sync(0xFFFFFFFFu, cnt, o);
        if (lane == 0) wred[warp] = cnt;
        __syncthreads();
        if (tid == 0) {
            int tot = 0;
            #pragma unroll
            for (int w = 0; w < 8; w++) tot += wred[w];
            bcast = tot;
        }
        __syncthreads();
    }
    const int cnt_gt  = bcast;
    const int need_eq = KPAIRS_ - cnt_gt;
    __syncthreads();

    // exclusive prefix of equal-count over contiguous 16-element chunks
    int eqc = 0;
    #pragma unroll
    for (int u = 0; u < 16; u++) eqc += (keys[tid*16 + u] == T);
    red[tid] = eqc;
    __syncthreads();
    if (tid == 0) {
        int run = 0;
        for (int t = 0; t < 256; t++) { const int v = red[t]; red[t] = run; run += v; }
    }
    __syncthreads();

    int rank = red[tid];
    float* o = out + (size_t)row * 4096;
    #pragma unroll
    for (int u = 0; u < 16; u++) {
        const unsigned int kk = keys[tid*16 + u];
        bool sel = (kk > T);
        if (kk == T) { sel = (rank < need_eq); rank++; }
        o[tid*16 + u] = sel ? 1.0f : 0.0f;
    }
}

// ---------------------------------------------------------------------------
extern "C" void kernel_launch(void* const* d_in, const int* in_sizes, int n_in,
                              void* d_out, int out_size)
{
    const float* q   = (const float*)d_in[0];
    const float* k   = (const float*)d_in[1];
    const float* w1  = (const float*)d_in[2];
    const float* b1  = (const float*)d_in[3];
    const float* w2  = (const float*)d_in[4];
    const float* b2  = (const float*)d_in[5];
    const float* w3  = (const float*)d_in[6];
    const float* b3  = (const float*)d_in[7];
    const float* wi1 = (const float*)d_in[8];
    const float* bi1 = (const float*)d_in[9];
    const float* wi2 = (const float*)d_in[10];
    const float* bi2 = (const float*)d_in[11];

    pool_mlp_kernel<<<B_*NB_*H_, 128>>>(q, k, w1, b1, w2, b2, w3, b3, wi1);
    interact_kernel<<<B_*NB_, 256>>>(bi1, wi2, bi2);
    topk_kernel<<<B_*H_, 256>>>((float*)d_out);
}

// round 9
// speedup vs baseline: 1.1481x; 1.1481x over previous
#include <cuda_runtime.h>
#include <math.h>

#define B_    4
#define S_    8192
#define H_    16
#define D_    128
#define NB_   64
#define BS_   128
#define HID_  32
#define HID2_ 16
#define KPAIRS_ 1024

// scratch (no cudaMalloc allowed)
__device__ float g_qimp [B_*NB_*H_];
__device__ float g_kimp [B_*NB_*H_];
__device__ float g_qpart[B_*NB_*H_*HID_];
__device__ float g_kpart[B_*NB_*H_*HID_];

// ---------------------------------------------------------------------------
// K1: block-mean pooling + importance MLP + interaction first-linear split.
// grid = B * NB * 4 = 1024 blocks; 128 threads.
// Block covers (b, blk, head-group of 4). Thread = (hh in 0..3, d4 in 0..31),
// loads float4, sums s sequentially (bit-identical order to the passing
// scalar version).
// ---------------------------------------------------------------------------
__global__ void pool_mlp_kernel(
    const float* __restrict__ q,  const float* __restrict__ k,
    const float* __restrict__ w1, const float* __restrict__ b1,
    const float* __restrict__ w2, const float* __restrict__ b2,
    const float* __restrict__ w3, const float* __restrict__ b3,
    const float* __restrict__ wi1)
{
    const int bid = blockIdx.x;
    const int b   = bid >> 8;
    const int blk = (bid >> 2) & 63;
    const int hg  = bid & 3;            // head group: heads 4*hg .. 4*hg+3
    const int tid = threadIdx.x;
    const int hh  = tid >> 5;           // 0..3
    const int h   = hg * 4 + hh;
    const int d4  = tid & 31;

    __shared__ float avg[2][4][D_];
    __shared__ float h1s[2][4][HID_];
    __shared__ float h2s[2][4][HID2_];

    const size_t base = (((size_t)b * S_ + (size_t)blk * BS_) * H_ + h) * D_ + d4 * 4;
    float4 sq = make_float4(0.f, 0.f, 0.f, 0.f);
    float4 sk = make_float4(0.f, 0.f, 0.f, 0.f);
    #pragma unroll 4
    for (int s = 0; s < BS_; s++) {
        const float4 a = *(const float4*)(q + base + (size_t)s * (H_*D_));
        const float4 c = *(const float4*)(k + base + (size_t)s * (H_*D_));
        sq.x += a.x; sq.y += a.y; sq.z += a.z; sq.w += a.w;
        sk.x += c.x; sk.y += c.y; sk.z += c.z; sk.w += c.w;
    }
    const float inv = 1.0f / 128.0f;
    sq.x *= inv; sq.y *= inv; sq.z *= inv; sq.w *= inv;
    sk.x *= inv; sk.y *= inv; sk.z *= inv; sk.w *= inv;
    *(float4*)&avg[0][hh][d4 * 4] = sq;
    *(float4*)&avg[1][hh][d4 * 4] = sk;
    __syncthreads();

    // layer 1: 512 dot products (256 importance + 256 interaction-split),
    // 4 per thread; uniform branch per c-iteration.
    #pragma unroll
    for (int c = 0; c < 4; c++) {
        const int dd   = tid + 128 * c;     // 0..511
        const int kind = dd >> 8;           // 0 = importance, 1 = interaction
        const int r    = dd & 255;
        const int t    = r >> 7;            // tensor (0=q, 1=k)
        const int hh2  = (r >> 5) & 3;
        const int j    = r & 31;
        const float* av = avg[t][hh2];
        if (kind == 0) {
            float acc = b1[j];
            #pragma unroll 8
            for (int d = 0; d < D_; d++) acc = fmaf(av[d], w1[d*HID_ + j], acc);
            h1s[t][hh2][j] = fmaxf(acc, 0.f);
        } else {
            float acc = 0.f;
            #pragma unroll 8
            for (int d = 0; d < D_; d++)
                acc = fmaf(av[d], wi1[(t*D_ + d)*HID_ + j], acc);
            float* gp = t ? g_kpart : g_qpart;
            gp[(((size_t)b*NB_ + blk)*H_ + (hg*4 + hh2))*HID_ + j] = acc;
        }
    }
    __syncthreads();

    // layer 2: 2*4*16 = 128 outputs, one per thread
    {
        const int t = tid >> 6;
        const int hh2 = (tid >> 4) & 3;
        const int j = tid & 15;
        float acc = b2[j];
        #pragma unroll
        for (int m = 0; m < HID_; m++) acc = fmaf(h1s[t][hh2][m], w2[m*HID2_ + j], acc);
        h2s[t][hh2][j] = fmaxf(acc, 0.f);
    }
    __syncthreads();

    // layer 3 + sigmoid: 8 outputs
    if (tid < 8) {
        const int t = tid >> 2;
        const int hh2 = tid & 3;
        float acc = b3[0];
        #pragma unroll
        for (int m = 0; m < HID2_; m++) acc = fmaf(h2s[t][hh2][m], w3[m], acc);
        const float imp = 1.f / (1.f + expf(-acc));
        float* gi = t ? g_kimp : g_qimp;
        gi[((size_t)b*NB_ + blk)*H_ + (hg*4 + hh2)] = imp;
    }
}

// ---------------------------------------------------------------------------
// K2+K3 fused: interaction MLP + combined score + exact top-1024-of-4096.
// One block per flat output row (b, xr): row = contiguous 4096 elements of
// combined at offset b*65536 + xr*4096; element t of the row decodes as
// i = 4*xr + (t>>10), j = (t>>4)&63, h = t&15. Output lands at the same
// contiguous offsets (verified: rel_err 0.0 in R5 with this mapping).
// grid = B*16 = 64 blocks, 256 threads, ~164 KB dynamic smem.
// ---------------------------------------------------------------------------
#define KPS_ROWS  (NB_*H_)      // 1024 rows of 32 (padded to 33)
#define QPS_ROWS  (4*H_)        // 64 rows
#define OFF_KPS   0
#define OFF_QPS   (KPS_ROWS*33)                 // 33792
#define OFF_KI    (OFF_QPS + QPS_ROWS*33)       // 35904
#define OFF_QI    (OFF_KI + NB_*H_)             // 36928
#define OFF_BW    (OFF_QI + QPS_ROWS)           // 36992
#define OFF_WV    (OFF_BW + HID_)               // 37024
#define OFF_KEYS  (OFF_WV + HID_)               // 37056
#define FUSED_SMEM_FLOATS (OFF_KEYS + 4096)     // 41152
#define FUSED_SMEM_BYTES  (FUSED_SMEM_FLOATS*4) // 164608

__global__ void interact_topk_kernel(
    const float* __restrict__ bi1,
    const float* __restrict__ wi2,
    const float* __restrict__ bi2,
    float* __restrict__ out)
{
    extern __shared__ float sm[];
    float* kps   = sm + OFF_KPS;   // [1024][33]
    float* qps   = sm + OFF_QPS;   // [64][33]
    float* kiA   = sm + OFF_KI;    // [1024]
    float* qiA   = sm + OFF_QI;    // [64]
    float* bw    = sm + OFF_BW;    // [32]
    float* wv    = sm + OFF_WV;    // [32]
    unsigned int* keys = (unsigned int*)(sm + OFF_KEYS); // [4096]

    __shared__ int wred[2][8];
    __shared__ int wsum[8];
    __shared__ int woff[8];

    const int row = blockIdx.x;       // b*16 + xr
    const int b   = row >> 4;
    const int xr  = row & 15;
    const int tid = threadIdx.x;
    const int lane = tid & 31;
    const int warp = tid >> 5;

    // --- stage kpart for batch b (coalesced), padded stride 33 ---
    {
        const float* src = g_kpart + (size_t)b * (NB_*H_*HID_);   // 32768 floats
        for (int it = 0; it < (NB_*H_*HID_)/256; it++) {
            const int idx = tid + 256 * it;
            kps[(idx >> 5)*33 + (idx & 31)] = src[idx];
        }
    }
    // --- stage qpart for i in [4*xr, 4*xr+4) ---
    {
        const float* src = g_qpart + ((size_t)b*NB_ + 4*xr) * (H_*HID_); // 2048 floats
        for (int it = 0; it < (4*H_*HID_)/256; it++) {
            const int idx = tid + 256 * it;
            qps[(idx >> 5)*33 + (idx & 31)] = src[idx];
        }
    }
    // --- importances + weights ---
    for (int t = tid; t < NB_*H_; t += 256) kiA[t] = g_kimp[(size_t)b*(NB_*H_) + t];
    if (tid < QPS_ROWS) qiA[tid] = g_qimp[((size_t)b*NB_ + 4*xr)*H_ + tid];
    if (tid < HID_) { bw[tid] = bi1[tid]; wv[tid] = wi2[tid]; }
    __syncthreads();

    // --- compute combined -> keys (arithmetic identical to passing K2) ---
    const float b2v = bi2[0];
    #pragma unroll 2
    for (int c = 0; c < 16; c++) {
        const int t    = tid + 256 * c;
        const int qrow = (t >> 10) * H_ + (t & 15);   // i_loc*16 + h
        const int krow = ((t >> 4) & 63) * H_ + (t & 15);
        const float* qph = &qps[qrow * 33];
        const float* kp  = &kps[krow * 33];
        float acc = b2v;
        #pragma unroll
        for (int m = 0; m < HID_; m++) {
            const float v = qph[m] + kp[m] + bw[m];
            acc = fmaf(fmaxf(v, 0.f), wv[m], acc);
        }
        const float inter = 1.f / (1.f + expf(-acc));
        const float ckey  = qiA[qrow] * kiA[krow] * inter;
        keys[t] = __float_as_uint(ckey);
    }
    __syncthreads();

    // --- binary search for T = 1024th largest key (1 barrier/iter) ---
    unsigned int lo = 0u, hi = 0x3F800000u;   // all keys in (0, 1]
    int it = 0;
    while (lo < hi) {
        const unsigned int mid = lo + ((hi - lo) >> 1) + 1u;
        int cnt = 0;
        #pragma unroll
        for (int u = 0; u < 16; u++) cnt += (keys[u*256 + tid] >= mid) ? 1 : 0;
        cnt = __reduce_add_sync(0xFFFFFFFFu, cnt);
        if (lane == 0) wred[it & 1][warp] = cnt;
        __syncthreads();
        int tot = 0;
        #pragma unroll
        for (int w = 0; w < 8; w++) tot += wred[it & 1][w];
        if (tot >= KPAIRS_) lo = mid; else hi = mid - 1u;
        it++;
    }
    const unsigned int T = lo;

    // --- count strictly greater ---
    int cnt_gt;
    {
        int cnt = 0;
        #pragma unroll
        for (int u = 0; u < 16; u++) cnt += (keys[u*256 + tid] > T) ? 1 : 0;
        cnt = __reduce_add_sync(0xFFFFFFFFu, cnt);
        if (lane == 0) wred[it & 1][warp] = cnt;
        __syncthreads();
        int tot = 0;
        #pragma unroll
        for (int w = 0; w < 8; w++) tot += wred[it & 1][w];
        cnt_gt = tot;
    }
    const int need_eq = KPAIRS_ - cnt_gt;

    // --- rank of equals in ascending flat order (contiguous chunks) ---
    unsigned int mykeys[16];
    int eqc = 0;
    #pragma unroll
    for (int u = 0; u < 16; u++) {
        mykeys[u] = keys[tid*16 + u];
        eqc += (mykeys[u] == T) ? 1 : 0;
    }
    int v = eqc;   // warp inclusive scan
    #pragma unroll
    for (int o = 1; o < 32; o <<= 1) {
        const int n = __shfl_up_sync(0xFFFFFFFFu, v, o);
        if (lane >= o) v += n;
    }
    if (lane == 31) wsum[warp] = v;
    __syncthreads();
    if (tid == 0) {
        int run = 0;
        #pragma unroll
        for (int w = 0; w < 8; w++) { woff[w] = run; run += wsum[w]; }
    }
    __syncthreads();

    int rank = woff[warp] + (v - eqc);
    float* o = out + (size_t)row * 4096 + tid * 16;
    #pragma unroll
    for (int u = 0; u < 16; u++) {
        const unsigned int kk = mykeys[u];
        bool sel = (kk > T);
        if (kk == T) { sel = (rank < need_eq); rank++; }
        o[u] = sel ? 1.0f : 0.0f;
    }
}

// ---------------------------------------------------------------------------
extern "C" void kernel_launch(void* const* d_in, const int* in_sizes, int n_in,
                              void* d_out, int out_size)
{
    const float* q   = (const float*)d_in[0];
    const float* k   = (const float*)d_in[1];
    const float* w1  = (const float*)d_in[2];
    const float* b1  = (const float*)d_in[3];
    const float* w2  = (const float*)d_in[4];
    const float* b2  = (const float*)d_in[5];
    const float* w3  = (const float*)d_in[6];
    const float* b3  = (const float*)d_in[7];
    const float* wi1 = (const float*)d_in[8];
    const float* bi1 = (const float*)d_in[9];
    const float* wi2 = (const float*)d_in[10];
    const float* bi2 = (const float*)d_in[11];

    cudaFuncSetAttribute(interact_topk_kernel,
                         cudaFuncAttributeMaxDynamicSharedMemorySize,
                         FUSED_SMEM_BYTES);

    pool_mlp_kernel<<<B_*NB_*4, 128>>>(q, k, w1, b1, w2, b2, w3, b3, wi1);
    interact_topk_kernel<<<B_*16, 256, FUSED_SMEM_BYTES>>>(bi1, wi2, bi2, (float*)d_out);
}